// round 4
// baseline (speedup 1.0000x reference)
#include <cuda_runtime.h>
#include <cuda_bf16.h>
#include <cstdint>

#define NN 50000
#define EE 800000

// ---------------- device scratch (no allocations allowed) ----------------
__device__ int   g_idx64;           // 1 if edge_index is int64, 0 if int32
__device__ int   g_counts[NN];
__device__ int   g_cursor[NN];
__device__ int   g_offsets[NN + 1];
__device__ float g_invdeg[NN];
__device__ int   g_ssrc[EE];
__device__ float g_mean[(size_t)NN * 256];
__device__ float g_h1[(size_t)NN * 256];
__device__ float g_h2[(size_t)NN * 128];
__device__ float g_h3[(size_t)NN * 128];
__device__ float g_Wc[128 * 8];
__device__ float g_bc[8];

// device-side buffer selection (no host symbol-address queries)
__device__ __forceinline__ const float* sel_buf(int sel, const float* x) {
    if (sel == 0) return x;
    if (sel == 1) return g_h1;
    if (sel == 2) return g_h2;
    return g_h3;
}
__device__ __forceinline__ float* sel_out(int sel) {
    if (sel == 1) return g_h1;
    if (sel == 2) return g_h2;
    return g_h3;
}

// ---------------- dtype probe: int64 vs int32 edge_index ----------------
// If int64 (all values < 50000), every odd 32-bit word (high half) is 0.
// If int32, odd words are random src indices -> OR is nonzero.
__global__ void probe_kernel(const int* __restrict__ ei) {
    if (threadIdx.x == 0) {
        int orv = 0;
        #pragma unroll 1
        for (int i = 1; i < 256; i += 2) orv |= ei[i];
        g_idx64 = (orv == 0) ? 1 : 0;
    }
}

// word index of element i of src / tgt under detected dtype
__device__ __forceinline__ int src_idx(const int* ei, int i) {
    return g_idx64 ? ei[2 * i] : ei[i];
}
__device__ __forceinline__ int tgt_idx(const int* ei, int i, int E) {
    return g_idx64 ? ei[2 * E + 2 * i] : ei[E + i];
}

// ---------------- CSR construction ----------------
__global__ void zero_counts_kernel(int n) {
    int i = blockIdx.x * blockDim.x + threadIdx.x;
    if (i < n) { g_counts[i] = 0; g_cursor[i] = 0; }
}

__global__ void hist_kernel(const int* __restrict__ ei, int E) {
    int i = blockIdx.x * blockDim.x + threadIdx.x;
    if (i < E) {
        int t = tgt_idx(ei, i, E);
        if ((unsigned)t < (unsigned)NN) atomicAdd(&g_counts[t], 1);
    }
}

// single-block inclusive scan over counts -> offsets, plus inv-degree
__global__ void scan_kernel(int n) {
    __shared__ int warpsums[32];
    __shared__ int carry_s;
    int tid = threadIdx.x;
    if (tid == 0) { carry_s = 0; g_offsets[0] = 0; }
    __syncthreads();
    for (int base = 0; base < n; base += 1024) {
        int i = base + tid;
        int v = (i < n) ? g_counts[i] : 0;
        int lane = tid & 31, wid = tid >> 5;
        int s = v;
        #pragma unroll
        for (int d = 1; d < 32; d <<= 1) {
            int t = __shfl_up_sync(0xFFFFFFFFu, s, d);
            if (lane >= d) s += t;
        }
        if (lane == 31) warpsums[wid] = s;
        __syncthreads();
        if (wid == 0) {
            int ws = warpsums[lane];
            #pragma unroll
            for (int d = 1; d < 32; d <<= 1) {
                int t = __shfl_up_sync(0xFFFFFFFFu, ws, d);
                if (lane >= d) ws += t;
            }
            warpsums[lane] = ws;
        }
        __syncthreads();
        int incl = s + (wid > 0 ? warpsums[wid - 1] : 0) + carry_s;
        if (i < n) {
            g_offsets[i + 1] = incl;
            g_invdeg[i] = 1.0f / fmaxf((float)v, 1.0f);
        }
        __syncthreads();
        if (tid == 1023) carry_s = incl;
        __syncthreads();
    }
}

__global__ void scatter_kernel(const int* __restrict__ ei, int E) {
    int i = blockIdx.x * blockDim.x + threadIdx.x;
    if (i < E) {
        int t = tgt_idx(ei, i, E);
        int s = src_idx(ei, i);
        if ((unsigned)t < (unsigned)NN && (unsigned)s < (unsigned)NN) {
            int pos = g_offsets[t] + atomicAdd(&g_cursor[t], 1);
            g_ssrc[pos] = s;
        }
    }
}

// ---------------- mean aggregation (gather over CSR) ----------------
// one warp per node; lane owns D/32 contiguous feature columns; out = g_mean
template <int D>
__global__ void aggregate_kernel(int sel, const float* __restrict__ x, int N) {
    const float* __restrict__ X = sel_buf(sel, x);
    int warp = (blockIdx.x * blockDim.x + threadIdx.x) >> 5;
    int lane = threadIdx.x & 31;
    if (warp >= N) return;
    int s = g_offsets[warp];
    int e = g_offsets[warp + 1];
    constexpr int V = D / 32;  // 2, 4, or 8
    float acc[V];
    #pragma unroll
    for (int u = 0; u < V; u++) acc[u] = 0.0f;

    for (int i = s; i < e; i++) {
        int srow = g_ssrc[i];
        const float* row = X + (size_t)srow * D + lane * V;
        if constexpr (V == 2) {
            float2 v = *(const float2*)row;
            acc[0] += v.x; acc[1] += v.y;
        } else {
            #pragma unroll
            for (int u = 0; u < V; u += 4) {
                float4 v = *(const float4*)(row + u);
                acc[u + 0] += v.x; acc[u + 1] += v.y;
                acc[u + 2] += v.z; acc[u + 3] += v.w;
            }
        }
    }
    float inv = g_invdeg[warp];
    float* o = g_mean + (size_t)warp * D + lane * V;
    if constexpr (V == 2) {
        float2 r; r.x = acc[0] * inv; r.y = acc[1] * inv;
        *(float2*)o = r;
    } else {
        #pragma unroll
        for (int u = 0; u < V; u += 4) {
            float4 r;
            r.x = acc[u + 0] * inv; r.y = acc[u + 1] * inv;
            r.z = acc[u + 2] * inv; r.w = acc[u + 3] * inv;
            *(float4*)(o + u) = r;
        }
    }
}

// ---------------- fused SAGE GEMM: C = relu([g_mean|A2] @ [Wl;Wr] + bias) --
// BM=128 BN=128 BK=16, 256 threads, 8x8 register tile per thread
#define GBM 128
#define GBN 128
#define GBK 16
#define GTM 8
#define GTN 8

__global__ __launch_bounds__(256, 2)
void sage_gemm_kernel(int selA2, const float* __restrict__ x, int selC,
                      int K1,                 // also = K2 (same feature dims)
                      const float* __restrict__ Wl,   // K1 x M
                      const float* __restrict__ Wr,   // K1 x M
                      const float* __restrict__ bias, // M
                      int N, int M) {
    const float* __restrict__ A1 = g_mean;
    const float* __restrict__ A2 = sel_buf(selA2, x);
    float* __restrict__ C = sel_out(selC);

    __shared__ float As[GBK][GBM + 1];
    __shared__ float Bs[GBK][GBN];

    int block_row = blockIdx.y * GBM;
    int block_col = blockIdx.x * GBN;
    int tid = threadIdx.x;
    int tr = tid / (GBN / GTN);  // 0..15
    int tc = tid % (GBN / GTN);  // 0..15

    float acc[GTM][GTN];
    #pragma unroll
    for (int i = 0; i < GTM; i++)
        #pragma unroll
        for (int j = 0; j < GTN; j++) acc[i][j] = 0.0f;

    const int K = 2 * K1;
    for (int k0 = 0; k0 < K; k0 += GBK) {
        #pragma unroll
        for (int l = 0; l < 2; l++) {
            int idx = tid + l * 256;      // 0..511
            int row = idx >> 2;           // 0..127
            int c4  = (idx & 3) * 4;      // 0,4,8,12
            int grow = block_row + row;
            int gk = k0 + c4;
            float4 v = make_float4(0.f, 0.f, 0.f, 0.f);
            if (grow < N) {
                if (gk < K1) v = *(const float4*)(A1 + (size_t)grow * K1 + gk);
                else         v = *(const float4*)(A2 + (size_t)grow * K1 + (gk - K1));
            }
            As[c4 + 0][row] = v.x; As[c4 + 1][row] = v.y;
            As[c4 + 2][row] = v.z; As[c4 + 3][row] = v.w;
        }
        #pragma unroll
        for (int l = 0; l < 2; l++) {
            int idx = tid + l * 256;
            int row = idx >> 5;           // 0..15
            int c4  = (idx & 31) * 4;     // 0..124
            int gk = k0 + row;
            const float* Wp = (gk < K1) ? (Wl + (size_t)gk * M)
                                        : (Wr + (size_t)(gk - K1) * M);
            *(float4*)(&Bs[row][c4]) = *(const float4*)(Wp + block_col + c4);
        }
        __syncthreads();

        #pragma unroll
        for (int kk = 0; kk < GBK; kk++) {
            float a[GTM], b[GTN];
            #pragma unroll
            for (int i = 0; i < GTM; i++) a[i] = As[kk][tr * GTM + i];
            #pragma unroll
            for (int j = 0; j < GTN; j++) b[j] = Bs[kk][tc * GTN + j];
            #pragma unroll
            for (int i = 0; i < GTM; i++)
                #pragma unroll
                for (int j = 0; j < GTN; j++) acc[i][j] += a[i] * b[j];
        }
        __syncthreads();
    }

    #pragma unroll
    for (int i = 0; i < GTM; i++) {
        int grow = block_row + tr * GTM + i;
        if (grow >= N) continue;
        #pragma unroll
        for (int j = 0; j < GTN; j += 4) {
            int gcol = block_col + tc * GTN + j;
            float4 r;
            r.x = fmaxf(acc[i][j + 0] + bias[gcol + 0], 0.f);
            r.y = fmaxf(acc[i][j + 1] + bias[gcol + 1], 0.f);
            r.z = fmaxf(acc[i][j + 2] + bias[gcol + 2], 0.f);
            r.w = fmaxf(acc[i][j + 3] + bias[gcol + 3], 0.f);
            *(float4*)(C + (size_t)grow * M + gcol) = r;
        }
    }
}

// ---------------- head: fold two linears into one 128x8 ----------------
__global__ void combine_head_kernel(const float* __restrict__ Wlin,
                                    const float* __restrict__ blin,
                                    const float* __restrict__ Wlin2,
                                    const float* __restrict__ blin2) {
    int tid = threadIdx.x;  // 1024 = 128*8
    int k = tid >> 3, j = tid & 7;
    float s = 0.f;
    #pragma unroll 8
    for (int l = 0; l < 128; l++) s += Wlin[k * 128 + l] * Wlin2[l * 8 + j];
    g_Wc[k * 8 + j] = s;
    if (k == 0) {
        float t = 0.f;
        for (int l = 0; l < 128; l++) t += blin[l] * Wlin2[l * 8 + j];
        g_bc[j] = t + blin2[j];
    }
}

__global__ void head_kernel(float* __restrict__ out, int N) {
    const float* __restrict__ h3 = g_h3;
    __shared__ float sW[128 * 8];
    __shared__ float sb[8];
    __shared__ float sh[32][132];  // pad -> conflict-free, float4-aligned

    for (int i = threadIdx.x; i < 1024; i += 256) sW[i] = g_Wc[i];
    if (threadIdx.x < 8) sb[threadIdx.x] = g_bc[threadIdx.x];

    int row0 = blockIdx.x * 32;
    for (int l = threadIdx.x; l < 1024; l += 256) {
        int r = l >> 5;
        int c4 = (l & 31) * 4;
        int grow = row0 + r;
        float4 v = (grow < N) ? *(const float4*)(h3 + (size_t)grow * 128 + c4)
                              : make_float4(0.f, 0.f, 0.f, 0.f);
        *(float4*)(&sh[r][c4]) = v;
    }
    __syncthreads();

    int r = threadIdx.x >> 3;  // 0..31
    int j = threadIdx.x & 7;
    float s = sb[j];
    #pragma unroll 8
    for (int k = 0; k < 128; k++) s += sh[r][k] * sW[k * 8 + j];
    int grow = row0 + r;
    if (grow < N) out[(size_t)grow * 8 + j] = s;
}

// ---------------- launch ----------------
extern "C" void kernel_launch(void* const* d_in, const int* in_sizes, int n_in,
                              void* d_out, int out_size) {
    const float* x    = (const float*)d_in[0];
    const int*   ei   = (const int*)d_in[1];   // int32 or int64, probed on device
    const float* Wf_l = (const float*)d_in[2];
    const float* bf   = (const float*)d_in[3];
    const float* Wf_r = (const float*)d_in[4];
    const float* W0_l = (const float*)d_in[5];
    const float* b0   = (const float*)d_in[6];
    const float* W0_r = (const float*)d_in[7];
    const float* W1_l = (const float*)d_in[8];
    const float* b1   = (const float*)d_in[9];
    const float* W1_r = (const float*)d_in[10];
    const float* W_lin  = (const float*)d_in[11];
    const float* b_lin  = (const float*)d_in[12];
    const float* W_lin2 = (const float*)d_in[13];
    const float* b_lin2 = (const float*)d_in[14];
    float* out = (float*)d_out;

    const int N = NN;
    const int E = in_sizes[1] / 2;  // element count is dtype-independent here

    // CSR build
    probe_kernel<<<1, 32>>>(ei);
    zero_counts_kernel<<<(N + 255) / 256, 256>>>(N);
    hist_kernel<<<(E + 255) / 256, 256>>>(ei, E);
    scan_kernel<<<1, 1024>>>(N);
    scatter_kernel<<<(E + 255) / 256, 256>>>(ei, E);

    const int aggBlocks = (N * 32 + 255) / 256;
    const int rowTiles = (N + GBM - 1) / GBM;  // 391

    // Layer 1: 64 -> 256   (A2 = x, C = g_h1)
    aggregate_kernel<64><<<aggBlocks, 256>>>(0, x, N);
    sage_gemm_kernel<<<dim3(256 / GBN, rowTiles), 256>>>(
        0, x, 1, 64, Wf_l, Wf_r, bf, N, 256);

    // Layer 2: 256 -> 128  (A2 = g_h1, C = g_h2)
    aggregate_kernel<256><<<aggBlocks, 256>>>(1, x, N);
    sage_gemm_kernel<<<dim3(128 / GBN, rowTiles), 256>>>(
        1, x, 2, 256, W0_l, W0_r, b0, N, 128);

    // Layer 3: 128 -> 128  (A2 = g_h2, C = g_h3)
    aggregate_kernel<128><<<aggBlocks, 256>>>(2, x, N);
    sage_gemm_kernel<<<dim3(128 / GBN, rowTiles), 256>>>(
        2, x, 3, 128, W1_l, W1_r, b1, N, 128);

    // Head (two linears folded into one)
    combine_head_kernel<<<1, 1024>>>(W_lin, b_lin, W_lin2, b_lin2);
    head_kernel<<<(N + 31) / 32, 256>>>(out, N);
}

// round 5
// speedup vs baseline: 1.2307x; 1.2307x over previous
#include <cuda_runtime.h>
#include <cuda_bf16.h>
#include <cstdint>

#define NN 50000
#define EE 800000

// ---------------- device scratch ----------------
__device__ int   g_idx64;
__device__ int   g_counts[NN];
__device__ int   g_cursor[NN];
__device__ int   g_offsets[NN + 1];
__device__ float g_invdeg[NN];
__device__ int   g_ssrc[EE];
__device__ int   g_part[64];
__device__ float g_mean64[(size_t)NN * 64];   // layer-1 neighbor mean
__device__ float g_z[(size_t)NN * 256];       // z = h @ [Wl||Wr] scratch
__device__ float g_h1[(size_t)NN * 256];
__device__ float g_h2[(size_t)NN * 128];
__device__ float g_h3[(size_t)NN * 128];
__device__ float g_Wc[128 * 8];
__device__ float g_bc[8];

__device__ __forceinline__ const float* sel_buf(int sel, const float* x) {
    if (sel == 0) return x;
    if (sel == 1) return g_h1;
    if (sel == 2) return g_h2;
    if (sel == 3) return g_h3;
    if (sel == 4) return g_z;
    return g_mean64;
}
__device__ __forceinline__ float* sel_out(int sel) {
    if (sel == 1) return g_h1;
    if (sel == 2) return g_h2;
    if (sel == 3) return g_h3;
    return g_z;
}

// ---------------- dtype probe: int64 vs int32 edge_index ----------------
__global__ void probe_kernel(const int* __restrict__ ei) {
    if (threadIdx.x == 0) {
        int orv = 0;
        #pragma unroll 1
        for (int i = 1; i < 256; i += 2) orv |= ei[i];
        g_idx64 = (orv == 0) ? 1 : 0;
    }
}
__device__ __forceinline__ int src_idx(const int* ei, int i) {
    return g_idx64 ? ei[2 * i] : ei[i];
}
__device__ __forceinline__ int tgt_idx(const int* ei, int i, int E) {
    return g_idx64 ? ei[2 * E + 2 * i] : ei[E + i];
}

// ---------------- CSR construction ----------------
__global__ void zero_counts_kernel(int n) {
    int i = blockIdx.x * blockDim.x + threadIdx.x;
    if (i < n) { g_counts[i] = 0; g_cursor[i] = 0; }
}

__global__ void hist_kernel(const int* __restrict__ ei, int E) {
    int i = blockIdx.x * blockDim.x + threadIdx.x;
    if (i < E) {
        int t = tgt_idx(ei, i, E);
        if ((unsigned)t < (unsigned)NN) atomicAdd(&g_counts[t], 1);
    }
}

// phase 1: per-block inclusive scan (1024 elems/block) + block totals
__global__ void scan_block_kernel(int n) {
    __shared__ int warpsums[32];
    int b = blockIdx.x, tid = threadIdx.x;
    int i = b * 1024 + tid;
    int v = (i < n) ? g_counts[i] : 0;
    int lane = tid & 31, wid = tid >> 5;
    int s = v;
    #pragma unroll
    for (int d = 1; d < 32; d <<= 1) {
        int t = __shfl_up_sync(0xFFFFFFFFu, s, d);
        if (lane >= d) s += t;
    }
    if (lane == 31) warpsums[wid] = s;
    __syncthreads();
    if (wid == 0) {
        int ws = warpsums[lane];
        #pragma unroll
        for (int d = 1; d < 32; d <<= 1) {
            int t = __shfl_up_sync(0xFFFFFFFFu, ws, d);
            if (lane >= d) ws += t;
        }
        warpsums[lane] = ws;
    }
    __syncthreads();
    int incl = s + (wid > 0 ? warpsums[wid - 1] : 0);
    if (i < n) {
        g_offsets[i + 1] = incl;
        g_invdeg[i] = 1.0f / fmaxf((float)v, 1.0f);
    }
    if (tid == 1023) g_part[b] = incl;
}

// phase 2: exclusive scan of <=64 block totals
__global__ void scan_part_kernel(int nb) {
    __shared__ int w0tot;
    int tid = threadIdx.x;  // 64 threads
    int v = (tid < nb) ? g_part[tid] : 0;
    int lane = tid & 31;
    int s = v;
    #pragma unroll
    for (int d = 1; d < 32; d <<= 1) {
        int t = __shfl_up_sync(0xFFFFFFFFu, s, d);
        if (lane >= d) s += t;
    }
    if (tid == 31) w0tot = s;
    __syncthreads();
    if (tid >= 32) s += w0tot;
    if (tid < nb) g_part[tid] = s - v;  // exclusive
}

// phase 3: add block offsets
__global__ void scan_add_kernel(int n) {
    int b = blockIdx.x;
    int i = b * 1024 + threadIdx.x;
    if (i < n) g_offsets[i + 1] += g_part[b];
    if (i == 0) g_offsets[0] = 0;
}

__global__ void scatter_kernel(const int* __restrict__ ei, int E) {
    int i = blockIdx.x * blockDim.x + threadIdx.x;
    if (i < E) {
        int t = tgt_idx(ei, i, E);
        int s = src_idx(ei, i);
        if ((unsigned)t < (unsigned)NN && (unsigned)s < (unsigned)NN) {
            int pos = g_offsets[t] + atomicAdd(&g_cursor[t], 1);
            g_ssrc[pos] = s;
        }
    }
}

// ---------------- layer-1 aggregation: mean of x (D=64) -> g_mean64 ------
__global__ void aggregate64_kernel(const float* __restrict__ X, int N) {
    int node = (blockIdx.x * blockDim.x + threadIdx.x) >> 5;
    int lane = threadIdx.x & 31;
    if (node >= N) return;
    int s = g_offsets[node], e = g_offsets[node + 1];
    float acc0 = 0.f, acc1 = 0.f;
    for (int i = s; i < e; i++) {
        int srow = g_ssrc[i];
        float2 v = *(const float2*)(X + (size_t)srow * 64 + lane * 2);
        acc0 += v.x; acc1 += v.y;
    }
    float inv = g_invdeg[node];
    float2 r; r.x = acc0 * inv; r.y = acc1 * inv;
    *(float2*)(g_mean64 + (size_t)node * 64 + lane * 2) = r;
}

// ---- fused layers 2/3: h_out = relu(mean_{nbr}(z_l) + bias + z_r) -------
// z is N x 256 (left half = h@Wl, right half = h@Wr); out is N x 128
__global__ void agg_combine_kernel(int selOut, const float* __restrict__ bias,
                                   int N) {
    const float* __restrict__ Z = g_z;
    float* __restrict__ O = sel_out(selOut);
    int node = (blockIdx.x * blockDim.x + threadIdx.x) >> 5;
    int lane = threadIdx.x & 31;
    if (node >= N) return;
    int s = g_offsets[node], e = g_offsets[node + 1];
    float acc[4] = {0.f, 0.f, 0.f, 0.f};
    for (int i = s; i < e; i++) {
        int srow = g_ssrc[i];
        float4 v = *(const float4*)(Z + (size_t)srow * 256 + lane * 4);
        acc[0] += v.x; acc[1] += v.y; acc[2] += v.z; acc[3] += v.w;
    }
    float inv = g_invdeg[node];
    float4 zr = *(const float4*)(Z + (size_t)node * 256 + 128 + lane * 4);
    float4 bv = *(const float4*)(bias + lane * 4);
    float4 r;
    r.x = fmaxf(acc[0] * inv + bv.x + zr.x, 0.f);
    r.y = fmaxf(acc[1] * inv + bv.y + zr.y, 0.f);
    r.z = fmaxf(acc[2] * inv + bv.z + zr.z, 0.f);
    r.w = fmaxf(acc[3] * inv + bv.w + zr.w, 0.f);
    *(float4*)(O + (size_t)node * 128 + lane * 4) = r;
}

// ---------------- GEMM: C(Nx256) = A @ B (+bias, relu) -------------------
// mode 0 (layer 1): A = [Aa | Ab] (k-split, each K1 wide), B = [Bl; Br]
//                   stacked in k, each K1 x 256.
// mode 1 (layers 2/3): A = Aa (K1 = Ktot wide), B n-split: cols 0-127 from
//                   Bl (K x 128), cols 128-255 from Br (K x 128).
// Double-buffered SMEM, BM=BN=128, BK=16, 256 thr, 8x8 reg tile.
#define GBM 128
#define GBN 128
#define GBK 16
#define APAD 4

__global__ __launch_bounds__(256, 2)
void sage_gemm_kernel(int mode, int selAa, int selAb, const float* __restrict__ x,
                      int selC, int K1, int Ktot,
                      const float* __restrict__ Bl,
                      const float* __restrict__ Br,
                      const float* __restrict__ bias,  // nullptr = no bias/relu
                      int N) {
    const float* __restrict__ Aa = sel_buf(selAa, x);
    const float* __restrict__ Ab = sel_buf(selAb, x);
    float* __restrict__ C = sel_out(selC);
    const int M = 256;

    __shared__ float As[2][GBK][GBM + APAD];
    __shared__ float Bs[2][GBK][GBN];

    int block_row = blockIdx.y * GBM;
    int block_col = blockIdx.x * GBN;
    int tid = threadIdx.x;
    int tr = tid >> 4;   // 0..15
    int tc = tid & 15;   // 0..15

    // per-thread load coords
    int arow = tid >> 2;            // 0..63  (+64 for second chunk)
    int ac4  = (tid & 3) * 4;       // 0,4,8,12
    int brow = tid >> 5;            // 0..7   (+8 for second chunk)
    int bc4  = (tid & 31) * 4;      // 0..124

    float4 aR[2], bR[2];

    // ---- load tile at k0 into registers ----
    auto load_tiles = [&](int k0) {
        #pragma unroll
        for (int l = 0; l < 2; l++) {
            int row = arow + l * 64;
            int grow = block_row + row;
            int gk = k0 + ac4;
            float4 v = make_float4(0.f, 0.f, 0.f, 0.f);
            if (grow < N) {
                if (gk < K1) v = *(const float4*)(Aa + (size_t)grow * K1 + gk);
                else         v = *(const float4*)(Ab + (size_t)grow * K1 + (gk - K1));
            }
            aR[l] = v;
        }
        #pragma unroll
        for (int l = 0; l < 2; l++) {
            int gk = k0 + brow + l * 8;
            const float* p;
            if (mode == 0) {
                p = (gk < K1) ? (Bl + (size_t)gk * M + block_col + bc4)
                              : (Br + (size_t)(gk - K1) * M + block_col + bc4);
            } else {
                const float* W = (block_col < 128) ? Bl : Br;
                p = W + (size_t)gk * 128 + (block_col & 127) + bc4;
            }
            bR[l] = *(const float4*)p;
        }
    };
    auto store_tiles = [&](int buf) {
        #pragma unroll
        for (int l = 0; l < 2; l++) {
            int row = arow + l * 64;
            As[buf][ac4 + 0][row] = aR[l].x;
            As[buf][ac4 + 1][row] = aR[l].y;
            As[buf][ac4 + 2][row] = aR[l].z;
            As[buf][ac4 + 3][row] = aR[l].w;
        }
        #pragma unroll
        for (int l = 0; l < 2; l++)
            *(float4*)(&Bs[buf][brow + l * 8][bc4]) = bR[l];
    };

    float acc[8][8];
    #pragma unroll
    for (int i = 0; i < 8; i++)
        #pragma unroll
        for (int j = 0; j < 8; j++) acc[i][j] = 0.0f;

    const int nt = Ktot / GBK;
    load_tiles(0);
    store_tiles(0);
    __syncthreads();

    for (int t = 0; t < nt; t++) {
        int cur = t & 1;
        if (t + 1 < nt) load_tiles((t + 1) * GBK);
        #pragma unroll
        for (int kk = 0; kk < GBK; kk++) {
            float a[8], b[8];
            *(float4*)(a)     = *(const float4*)(&As[cur][kk][tr * 8]);
            *(float4*)(a + 4) = *(const float4*)(&As[cur][kk][tr * 8 + 4]);
            *(float4*)(b)     = *(const float4*)(&Bs[cur][kk][tc * 8]);
            *(float4*)(b + 4) = *(const float4*)(&Bs[cur][kk][tc * 8 + 4]);
            #pragma unroll
            for (int i = 0; i < 8; i++)
                #pragma unroll
                for (int j = 0; j < 8; j++) acc[i][j] += a[i] * b[j];
        }
        if (t + 1 < nt) {
            store_tiles(cur ^ 1);
            __syncthreads();
        }
    }

    const bool hasBias = (bias != nullptr);
    #pragma unroll
    for (int i = 0; i < 8; i++) {
        int grow = block_row + tr * 8 + i;
        if (grow >= N) continue;
        #pragma unroll
        for (int j = 0; j < 8; j += 4) {
            int gcol = block_col + tc * 8 + j;
            float4 r;
            r.x = acc[i][j + 0]; r.y = acc[i][j + 1];
            r.z = acc[i][j + 2]; r.w = acc[i][j + 3];
            if (hasBias) {
                r.x = fmaxf(r.x + bias[gcol + 0], 0.f);
                r.y = fmaxf(r.y + bias[gcol + 1], 0.f);
                r.z = fmaxf(r.z + bias[gcol + 2], 0.f);
                r.w = fmaxf(r.w + bias[gcol + 3], 0.f);
            }
            *(float4*)(C + (size_t)grow * 256 + gcol) = r;
        }
    }
}

// ---------------- head: fold two linears into one 128x8 ----------------
__global__ void combine_head_kernel(const float* __restrict__ Wlin,
                                    const float* __restrict__ blin,
                                    const float* __restrict__ Wlin2,
                                    const float* __restrict__ blin2) {
    int tid = threadIdx.x;  // 1024 = 128*8
    int k = tid >> 3, j = tid & 7;
    float s = 0.f;
    #pragma unroll 8
    for (int l = 0; l < 128; l++) s += Wlin[k * 128 + l] * Wlin2[l * 8 + j];
    g_Wc[k * 8 + j] = s;
    if (k == 0) {
        float t = 0.f;
        for (int l = 0; l < 128; l++) t += blin[l] * Wlin2[l * 8 + j];
        g_bc[j] = t + blin2[j];
    }
}

__global__ void head_kernel(float* __restrict__ out, int N) {
    const float* __restrict__ h3 = g_h3;
    __shared__ float sW[128 * 8];
    __shared__ float sb[8];
    __shared__ float sh[32][132];

    for (int i = threadIdx.x; i < 1024; i += 256) sW[i] = g_Wc[i];
    if (threadIdx.x < 8) sb[threadIdx.x] = g_bc[threadIdx.x];

    int row0 = blockIdx.x * 32;
    for (int l = threadIdx.x; l < 1024; l += 256) {
        int r = l >> 5;
        int c4 = (l & 31) * 4;
        int grow = row0 + r;
        float4 v = (grow < N) ? *(const float4*)(h3 + (size_t)grow * 128 + c4)
                              : make_float4(0.f, 0.f, 0.f, 0.f);
        *(float4*)(&sh[r][c4]) = v;
    }
    __syncthreads();

    int r = threadIdx.x >> 3;
    int j = threadIdx.x & 7;
    float s = sb[j];
    #pragma unroll 8
    for (int k = 0; k < 128; k++) s += sh[r][k] * sW[k * 8 + j];
    int grow = row0 + r;
    if (grow < N) out[(size_t)grow * 8 + j] = s;
}

// ---------------- launch ----------------
extern "C" void kernel_launch(void* const* d_in, const int* in_sizes, int n_in,
                              void* d_out, int out_size) {
    const float* x    = (const float*)d_in[0];
    const int*   ei   = (const int*)d_in[1];
    const float* Wf_l = (const float*)d_in[2];
    const float* bf   = (const float*)d_in[3];
    const float* Wf_r = (const float*)d_in[4];
    const float* W0_l = (const float*)d_in[5];
    const float* b0   = (const float*)d_in[6];
    const float* W0_r = (const float*)d_in[7];
    const float* W1_l = (const float*)d_in[8];
    const float* b1   = (const float*)d_in[9];
    const float* W1_r = (const float*)d_in[10];
    const float* W_lin  = (const float*)d_in[11];
    const float* b_lin  = (const float*)d_in[12];
    const float* W_lin2 = (const float*)d_in[13];
    const float* b_lin2 = (const float*)d_in[14];
    float* out = (float*)d_out;

    const int N = NN;
    const int E = in_sizes[1] / 2;
    const int scanBlocks = (N + 1023) / 1024;  // 49

    // CSR build
    probe_kernel<<<1, 32>>>(ei);
    zero_counts_kernel<<<(N + 255) / 256, 256>>>(N);
    hist_kernel<<<(E + 255) / 256, 256>>>(ei, E);
    scan_block_kernel<<<scanBlocks, 1024>>>(N);
    scan_part_kernel<<<1, 64>>>(scanBlocks);
    scan_add_kernel<<<scanBlocks, 1024>>>(N);
    scatter_kernel<<<(E + 255) / 256, 256>>>(ei, E);

    const int aggBlocks = (N * 32 + 255) / 256;
    const int rowTiles = (N + GBM - 1) / GBM;  // 391
    dim3 gemmGrid(2, rowTiles);

    // Layer 1: h1 = relu([mean64(x) | x] @ [Wf_l;Wf_r] + bf)
    aggregate64_kernel<<<aggBlocks, 256>>>(x, N);
    sage_gemm_kernel<<<gemmGrid, 256>>>(0, 5, 0, x, 1, 64, 128,
                                        Wf_l, Wf_r, bf, N);

    // Layer 2: z = h1 @ [W0_l || W0_r]; h2 = relu(mean(z_l) + b0 + z_r)
    sage_gemm_kernel<<<gemmGrid, 256>>>(1, 1, 1, x, 4, 256, 256,
                                        W0_l, W0_r, nullptr, N);
    agg_combine_kernel<<<aggBlocks, 256>>>(2, b0, N);

    // Layer 3: z = h2 @ [W1_l || W1_r]; h3 = relu(mean(z_l) + b1 + z_r)
    sage_gemm_kernel<<<gemmGrid, 256>>>(1, 2, 2, x, 4, 128, 128,
                                        W1_l, W1_r, nullptr, N);
    agg_combine_kernel<<<aggBlocks, 256>>>(3, b1, N);

    // Head
    combine_head_kernel<<<1, 1024>>>(W_lin, b_lin, W_lin2, b_lin2);
    head_kernel<<<(N + 31) / 32, 256>>>(out, N);
}